// round 1
// baseline (speedup 1.0000x reference)
#include <cuda_runtime.h>
#include <math.h>

#define HIDDEN 2048
#define NHEADS 16
#define HDIM   128
#define BATCH  2
#define SEQ    2048
#define ROWS   (BATCH*SEQ)             // 4096
#define SCALE  0.08838834764831845f    // 1/sqrt(128)

// Scratch (allocation-guard-safe): 4 x 32 MB
__device__ float g_Q[ROWS*HIDDEN];
__device__ float g_K[ROWS*HIDDEN];
__device__ float g_V[ROWS*HIDDEN];
__device__ float g_C[ROWS*HIDDEN];

// ---------------------------------------------------------------------------
// GEMM:  C[M,N] = A[M,K] @ W[N,K]^T + bias   (torch Linear convention)
// 128x128 block tile, BK=16, 8x8 per thread, f32x2 packed FMA inner loop.
// ---------------------------------------------------------------------------
#define BM 128
#define BN 128
#define BK 16
#define TM 8
#define TN 8

__global__ __launch_bounds__(256) void sgemm_nt_bias(
    const float* __restrict__ A, const float* __restrict__ W,
    const float* __restrict__ bias, float* __restrict__ C,
    int M, int N, int K)
{
    __shared__ float As[BK][BM];   // A stored transposed: As[k][m]
    __shared__ float Ws[BK][BN];   // W stored transposed: Ws[k][n]

    const int tid  = threadIdx.x;
    const int brow = blockIdx.y * BM;
    const int bcol = blockIdx.x * BN;
    const int trow = (tid / 16) * TM;
    const int tcol = (tid % 16) * TN;

    const int lrow = tid >> 2;          // 0..63
    const int lcol = (tid & 3) * 4;     // 0,4,8,12

    unsigned long long acc[TM][TN/2];   // packed f32x2 accumulators
    #pragma unroll
    for (int i = 0; i < TM; i++)
        #pragma unroll
        for (int j = 0; j < TN/2; j++) acc[i][j] = 0ull;

    for (int k0 = 0; k0 < K; k0 += BK) {
        #pragma unroll
        for (int h = 0; h < 2; h++) {
            int r = lrow + h * 64;
            float4 va = *(const float4*)&A[(size_t)(brow + r) * K + k0 + lcol];
            As[lcol+0][r] = va.x; As[lcol+1][r] = va.y;
            As[lcol+2][r] = va.z; As[lcol+3][r] = va.w;
            float4 vw = *(const float4*)&W[(size_t)(bcol + r) * K + k0 + lcol];
            Ws[lcol+0][r] = vw.x; Ws[lcol+1][r] = vw.y;
            Ws[lcol+2][r] = vw.z; Ws[lcol+3][r] = vw.w;
        }
        __syncthreads();

        #pragma unroll
        for (int k = 0; k < BK; k++) {
            float ra[TM];
            *(float4*)&ra[0] = *(const float4*)&As[k][trow];
            *(float4*)&ra[4] = *(const float4*)&As[k][trow + 4];
            unsigned long long bb[TN/2];  // contiguous pairs of W values
            bb[0] = *(const unsigned long long*)&Ws[k][tcol + 0];
            bb[1] = *(const unsigned long long*)&Ws[k][tcol + 2];
            bb[2] = *(const unsigned long long*)&Ws[k][tcol + 4];
            bb[3] = *(const unsigned long long*)&Ws[k][tcol + 6];
            #pragma unroll
            for (int i = 0; i < TM; i++) {
                unsigned long long aa;
                asm("mov.b64 %0, {%1, %1};" : "=l"(aa) : "f"(ra[i]));
                #pragma unroll
                for (int j = 0; j < TN/2; j++) {
                    asm("fma.rn.f32x2 %0, %1, %2, %0;"
                        : "+l"(acc[i][j]) : "l"(aa), "l"(bb[j]));
                }
            }
        }
        __syncthreads();
    }

    #pragma unroll
    for (int i = 0; i < TM; i++) {
        float out[TN];
        #pragma unroll
        for (int j = 0; j < TN/2; j++) {
            float2 p = *(float2*)&acc[i][j];
            out[2*j]   = p.x + bias[bcol + tcol + 2*j];
            out[2*j+1] = p.y + bias[bcol + tcol + 2*j + 1];
        }
        size_t row = (size_t)(brow + trow + i) * N + bcol + tcol;
        *(float4*)&C[row]     = *(float4*)&out[0];
        *(float4*)&C[row + 4] = *(float4*)&out[4];
    }
}

// ---------------------------------------------------------------------------
// Flash attention: per-(q-tile, head, batch) block, online softmax.
// BQ=64 q-rows, BK=64 keys per iteration, d=128, 256 threads.
// ---------------------------------------------------------------------------
#define AQ 64
#define AK 64
#define ATHREADS 256
#define ATT_SMEM_FLOATS (3*AQ*HDIM + AQ*(AK+1) + 3*AQ)
#define ATT_SMEM (ATT_SMEM_FLOATS * sizeof(float))

__global__ __launch_bounds__(ATHREADS) void attn_kernel(
    const float* __restrict__ Q, const float* __restrict__ K,
    const float* __restrict__ V, const float* __restrict__ mask,
    float* __restrict__ O)
{
    extern __shared__ float sm[];
    float* sQ = sm;                       // AQ*HDIM
    float* sK = sQ + AQ*HDIM;             // AK*HDIM
    float* sV = sK + AQ*HDIM;             // AK*HDIM
    float* sS = sV + AQ*HDIM;             // AQ*(AK+1)
    float* sM = sS + AQ*(AK+1);
    float* sL = sM + AQ;
    float* sF = sL + AQ;

    const int tid = threadIdx.x;
    const int qt = blockIdx.x, h = blockIdx.y, b = blockIdx.z;
    const size_t base = ((size_t)b * SEQ) * HIDDEN + (size_t)h * HDIM;

    // Load Q tile (stays resident)
    for (int it = tid; it < AQ*HDIM/4; it += ATHREADS) {
        int r  = it >> 5;            // / (HDIM/4)
        int c4 = (it & 31) << 2;
        ((float4*)sQ)[it] = *(const float4*)&Q[base + (size_t)(qt*AQ + r)*HIDDEN + c4];
    }
    if (tid < AQ) { sM[tid] = -1e30f; sL[tid] = 0.f; }

    const int rg  = tid >> 4;     // 0..15
    const int cg  = tid & 15;     // 0..15
    const int r0  = rg * 4;       // row group (4 rows)
    const int sc0 = cg * 4;       // score col group (4 cols)
    const int oc0 = cg * 8;       // output col group (8 cols)

    float o[4][8];
    #pragma unroll
    for (int i = 0; i < 4; i++)
        #pragma unroll
        for (int j = 0; j < 8; j++) o[i][j] = 0.f;

    for (int kt = 0; kt < SEQ/AK; kt++) {
        // Load K/V tiles
        for (int it = tid; it < AK*HDIM/4; it += ATHREADS) {
            int r  = it >> 5;
            int c4 = (it & 31) << 2;
            size_t g = base + (size_t)(kt*AK + r)*HIDDEN + c4;
            ((float4*)sK)[it] = *(const float4*)&K[g];
            ((float4*)sV)[it] = *(const float4*)&V[g];
        }
        __syncthreads();

        // S = Q K^T  (each thread: 4x4 tile)
        float s[4][4];
        #pragma unroll
        for (int i = 0; i < 4; i++)
            #pragma unroll
            for (int j = 0; j < 4; j++) s[i][j] = 0.f;
        for (int d = 0; d < HDIM; d += 4) {
            float4 qv[4], kv[4];
            #pragma unroll
            for (int i = 0; i < 4; i++) qv[i] = *(const float4*)&sQ[(r0+i)*HDIM + d];
            #pragma unroll
            for (int j = 0; j < 4; j++) kv[j] = *(const float4*)&sK[(sc0+j)*HDIM + d];
            #pragma unroll
            for (int i = 0; i < 4; i++)
                #pragma unroll
                for (int j = 0; j < 4; j++)
                    s[i][j] += qv[i].x*kv[j].x + qv[i].y*kv[j].y
                             + qv[i].z*kv[j].z + qv[i].w*kv[j].w;
        }
        #pragma unroll
        for (int j = 0; j < 4; j++) {
            float mv = mask[(size_t)b*SEQ + kt*AK + sc0 + j];
            #pragma unroll
            for (int i = 0; i < 4; i++)
                sS[(r0+i)*(AK+1) + sc0 + j] = s[i][j]*SCALE + mv;
        }
        __syncthreads();

        // Online softmax row stats (one thread per row)
        if (tid < AQ) {
            float* row = &sS[tid*(AK+1)];
            float m_old = sM[tid];
            float mt = m_old;
            for (int c = 0; c < AK; c++) mt = fmaxf(mt, row[c]);
            float f = __expf(m_old - mt);
            float l = sL[tid] * f;
            for (int c = 0; c < AK; c++) { float p = __expf(row[c] - mt); row[c] = p; l += p; }
            sM[tid] = mt; sL[tid] = l; sF[tid] = f;
        }
        __syncthreads();

        // Rescale + O += P V
        float f4[4];
        #pragma unroll
        for (int i = 0; i < 4; i++) f4[i] = sF[r0+i];
        #pragma unroll
        for (int i = 0; i < 4; i++)
            #pragma unroll
            for (int j = 0; j < 8; j++) o[i][j] *= f4[i];

        for (int k = 0; k < AK; k++) {
            float p[4];
            #pragma unroll
            for (int i = 0; i < 4; i++) p[i] = sS[(r0+i)*(AK+1) + k];
            float4 v0 = *(const float4*)&sV[k*HDIM + oc0];
            float4 v1 = *(const float4*)&sV[k*HDIM + oc0 + 4];
            #pragma unroll
            for (int i = 0; i < 4; i++) {
                o[i][0] += p[i]*v0.x; o[i][1] += p[i]*v0.y;
                o[i][2] += p[i]*v0.z; o[i][3] += p[i]*v0.w;
                o[i][4] += p[i]*v1.x; o[i][5] += p[i]*v1.y;
                o[i][6] += p[i]*v1.z; o[i][7] += p[i]*v1.w;
            }
        }
        __syncthreads();
    }

    // Normalize and write ctx in [B*S, HIDDEN] layout (heads re-interleaved)
    #pragma unroll
    for (int i = 0; i < 4; i++) {
        float inv = 1.f / sL[r0+i];
        float out[8];
        #pragma unroll
        for (int j = 0; j < 8; j++) out[j] = o[i][j] * inv;
        size_t g = base + (size_t)(qt*AQ + r0 + i)*HIDDEN + oc0;
        *(float4*)&O[g]     = *(float4*)&out[0];
        *(float4*)&O[g + 4] = *(float4*)&out[4];
    }
}

// ---------------------------------------------------------------------------
extern "C" void kernel_launch(void* const* d_in, const int* in_sizes, int n_in,
                              void* d_out, int out_size) {
    const float* X    = (const float*)d_in[0];
    const float* mask = (const float*)d_in[1];
    const float* Wq   = (const float*)d_in[2];
    const float* bq   = (const float*)d_in[3];
    const float* Wk   = (const float*)d_in[4];
    const float* bk   = (const float*)d_in[5];
    const float* Wv   = (const float*)d_in[6];
    const float* bv   = (const float*)d_in[7];
    const float* Wo   = (const float*)d_in[8];
    const float* bo   = (const float*)d_in[9];
    float* out = (float*)d_out;

    float *qp, *kp, *vp, *cp;
    cudaGetSymbolAddress((void**)&qp, g_Q);
    cudaGetSymbolAddress((void**)&kp, g_K);
    cudaGetSymbolAddress((void**)&vp, g_V);
    cudaGetSymbolAddress((void**)&cp, g_C);

    dim3 ggrid(HIDDEN/BN, ROWS/BM);   // (16, 32)
    sgemm_nt_bias<<<ggrid, 256>>>(X, Wq, bq, qp, ROWS, HIDDEN, HIDDEN);
    sgemm_nt_bias<<<ggrid, 256>>>(X, Wk, bk, kp, ROWS, HIDDEN, HIDDEN);
    sgemm_nt_bias<<<ggrid, 256>>>(X, Wv, bv, vp, ROWS, HIDDEN, HIDDEN);

    cudaFuncSetAttribute(attn_kernel, cudaFuncAttributeMaxDynamicSharedMemorySize,
                         (int)ATT_SMEM);
    dim3 agrid(SEQ/AQ, NHEADS, BATCH);  // (32, 16, 2)
    attn_kernel<<<agrid, ATHREADS, ATT_SMEM>>>(qp, kp, vp, mask, cp);

    sgemm_nt_bias<<<ggrid, 256>>>(cp, Wo, bo, out, ROWS, HIDDEN, HIDDEN);
}

// round 2
// speedup vs baseline: 3.0755x; 3.0755x over previous
#include <cuda_runtime.h>
#include <math.h>

#define HIDDEN 2048
#define NHEADS 16
#define HDIM   128
#define BATCH  2
#define SEQ    2048
#define ROWS   (BATCH*SEQ)             // 4096
#define SCALE  0.08838834764831845f    // 1/sqrt(128)

// Scratch (allocation-guard-safe): 4 x 32 MB
__device__ float g_Q[ROWS*HIDDEN];
__device__ float g_K[ROWS*HIDDEN];
__device__ float g_V[ROWS*HIDDEN];
__device__ float g_C[ROWS*HIDDEN];

__device__ __forceinline__ unsigned f2tf(float f) {
    unsigned u; asm("cvt.rna.tf32.f32 %0, %1;" : "=r"(u) : "f"(f)); return u;
}

__device__ __forceinline__ void mma8(float* c, const unsigned* a, const unsigned* b) {
    asm volatile(
        "mma.sync.aligned.m16n8k8.row.col.f32.tf32.tf32.f32 "
        "{%0,%1,%2,%3}, {%4,%5,%6,%7}, {%8,%9}, {%0,%1,%2,%3};"
        : "+f"(c[0]), "+f"(c[1]), "+f"(c[2]), "+f"(c[3])
        : "r"(a[0]), "r"(a[1]), "r"(a[2]), "r"(a[3]), "r"(b[0]), "r"(b[1]));
}

// ---------------------------------------------------------------------------
// TF32 tensor-core GEMM:  C[M,N] = A[M,K] @ W[N,K]^T + bias
// 128x128x16 block tile, 8 warps (2 row x 4 col), each warp 64x32 output
// via 4x4 m16n8k8 MMA tiles. Register-prefetched gmem loads.
// ---------------------------------------------------------------------------
#define BM 128
#define BN 128
#define BK 16
#define APAD 4

__global__ __launch_bounds__(256) void tf32_gemm_nt_bias(
    const float* __restrict__ A, const float* __restrict__ W,
    const float* __restrict__ bias, float* __restrict__ C,
    int M, int N, int K)
{
    __shared__ unsigned sA[BK][BM + APAD];   // sA[k][m] (tf32 bits)
    __shared__ unsigned sB[BK][BN + APAD];   // sB[k][n] = W[n][k] (tf32 bits)

    const int tid  = threadIdx.x;
    const int lane = tid & 31;
    const int warp = tid >> 5;
    const int g    = lane >> 2;      // 0..7
    const int l4   = lane & 3;       // 0..3
    const int wr   = warp & 1;       // 2 row-warps
    const int wc   = warp >> 1;      // 4 col-warps
    const int mb   = wr * 64;
    const int nb   = wc * 32;
    const int brow = blockIdx.y * BM;
    const int bcol = blockIdx.x * BN;
    const int lr   = tid >> 2;           // 0..63
    const int lc   = (tid & 3) * 4;      // 0,4,8,12

    float acc[4][4][4];
    #pragma unroll
    for (int i = 0; i < 4; i++)
        #pragma unroll
        for (int j = 0; j < 4; j++)
            #pragma unroll
            for (int t = 0; t < 4; t++) acc[i][j][t] = 0.f;

    float4 pa[2], pb[2];
    #pragma unroll
    for (int h = 0; h < 2; h++) {
        pa[h] = *(const float4*)&A[(size_t)(brow + lr + h*64) * K + lc];
        pb[h] = *(const float4*)&W[(size_t)(bcol + lr + h*64) * K + lc];
    }

    for (int k0 = 0; k0 < K; k0 += BK) {
        #pragma unroll
        for (int h = 0; h < 2; h++) {
            int r = lr + h * 64;
            sA[lc+0][r] = f2tf(pa[h].x); sA[lc+1][r] = f2tf(pa[h].y);
            sA[lc+2][r] = f2tf(pa[h].z); sA[lc+3][r] = f2tf(pa[h].w);
            sB[lc+0][r] = f2tf(pb[h].x); sB[lc+1][r] = f2tf(pb[h].y);
            sB[lc+2][r] = f2tf(pb[h].z); sB[lc+3][r] = f2tf(pb[h].w);
        }
        __syncthreads();

        if (k0 + BK < K) {
            #pragma unroll
            for (int h = 0; h < 2; h++) {
                pa[h] = *(const float4*)&A[(size_t)(brow + lr + h*64) * K + k0 + BK + lc];
                pb[h] = *(const float4*)&W[(size_t)(bcol + lr + h*64) * K + k0 + BK + lc];
            }
        }

        #pragma unroll
        for (int ks = 0; ks < BK; ks += 8) {
            unsigned af[4][4], bf[4][2];
            #pragma unroll
            for (int i = 0; i < 4; i++) {
                af[i][0] = sA[ks + l4    ][mb + i*16 + g    ];
                af[i][1] = sA[ks + l4    ][mb + i*16 + g + 8];
                af[i][2] = sA[ks + l4 + 4][mb + i*16 + g    ];
                af[i][3] = sA[ks + l4 + 4][mb + i*16 + g + 8];
            }
            #pragma unroll
            for (int j = 0; j < 4; j++) {
                bf[j][0] = sB[ks + l4    ][nb + j*8 + g];
                bf[j][1] = sB[ks + l4 + 4][nb + j*8 + g];
            }
            #pragma unroll
            for (int i = 0; i < 4; i++)
                #pragma unroll
                for (int j = 0; j < 4; j++)
                    mma8(acc[i][j], af[i], bf[j]);
        }
        __syncthreads();
    }

    #pragma unroll
    for (int i = 0; i < 4; i++) {
        int row = brow + mb + i*16 + g;
        #pragma unroll
        for (int j = 0; j < 4; j++) {
            int col = bcol + nb + j*8 + 2*l4;
            float b0 = bias[col], b1 = bias[col + 1];
            float2 v0 = { acc[i][j][0] + b0, acc[i][j][1] + b1 };
            float2 v1 = { acc[i][j][2] + b0, acc[i][j][3] + b1 };
            *(float2*)&C[(size_t)row * N + col]       = v0;
            *(float2*)&C[(size_t)(row + 8) * N + col] = v1;
        }
    }
}

// ---------------------------------------------------------------------------
// Flash attention with TF32 MMA for QK^T and PV.
// Per block: 64 q-rows, one (head, batch); loops over 64-key tiles.
// 8 warps: warp wr=warp&3 owns 16 q-rows; wc=warp>>2 owns half of keys
// (scores) / half of head-dim (output).
// ---------------------------------------------------------------------------
#define AQ 64
#define AK 64
#define QW 132     // HDIM + 4 pad
#define SW 68      // AK + 4 pad
#define ATT_SMEM ((3*AQ*QW + AQ*SW + 3*AQ) * 4)

__global__ __launch_bounds__(256) void attn_tf32(
    const float* __restrict__ Q, const float* __restrict__ K,
    const float* __restrict__ V, const float* __restrict__ mask,
    float* __restrict__ O)
{
    extern __shared__ unsigned shm[];
    unsigned* sQ = shm;                 // [AQ][QW] tf32 bits
    unsigned* sK = sQ + AQ*QW;          // [AK][QW]
    unsigned* sV = sK + AQ*QW;          // [AK][QW]
    float* sS = (float*)(sV + AQ*QW);   // [AQ][SW]
    float* sM = sS + AQ*SW;
    float* sL = sM + AQ;
    float* sF = sL + AQ;

    const int tid  = threadIdx.x;
    const int lane = tid & 31;
    const int warp = tid >> 5;
    const int g    = lane >> 2;
    const int l4   = lane & 3;
    const int wr   = warp & 3;
    const int wc   = warp >> 2;
    const int mb   = wr * 16;
    const int nbs  = wc * 32;   // score cols (keys)
    const int nbo  = wc * 64;   // output cols (head dim)
    const int qt = blockIdx.x, h = blockIdx.y, b = blockIdx.z;
    const size_t base = (size_t)b * SEQ * HIDDEN + (size_t)h * HDIM;

    // Load Q tile (resident), converting to tf32
    for (int it = tid; it < AQ*HDIM/4; it += 256) {
        int r = it >> 5, c = (it & 31) * 4;
        float4 v = *(const float4*)&Q[base + (size_t)(qt*AQ + r)*HIDDEN + c];
        unsigned* p = &sQ[r*QW + c];
        p[0] = f2tf(v.x); p[1] = f2tf(v.y); p[2] = f2tf(v.z); p[3] = f2tf(v.w);
    }
    if (tid < AQ) { sM[tid] = -1e30f; sL[tid] = 0.f; }

    float oacc[8][4];
    #pragma unroll
    for (int j = 0; j < 8; j++)
        #pragma unroll
        for (int t = 0; t < 4; t++) oacc[j][t] = 0.f;

    for (int kt = 0; kt < SEQ/AK; kt++) {
        // Load K/V tiles
        for (int it = tid; it < AK*HDIM/4; it += 256) {
            int r = it >> 5, c = (it & 31) * 4;
            size_t gidx = base + (size_t)(kt*AK + r)*HIDDEN + c;
            float4 kv = *(const float4*)&K[gidx];
            float4 vv = *(const float4*)&V[gidx];
            unsigned* pk = &sK[r*QW + c];
            pk[0] = f2tf(kv.x); pk[1] = f2tf(kv.y); pk[2] = f2tf(kv.z); pk[3] = f2tf(kv.w);
            unsigned* pv = &sV[r*QW + c];
            pv[0] = f2tf(vv.x); pv[1] = f2tf(vv.y); pv[2] = f2tf(vv.z); pv[3] = f2tf(vv.w);
        }
        __syncthreads();

        // Scores: S[mb..mb+15][nbs..nbs+31] = Q K^T
        float sacc[4][4];
        #pragma unroll
        for (int j = 0; j < 4; j++)
            #pragma unroll
            for (int t = 0; t < 4; t++) sacc[j][t] = 0.f;

        #pragma unroll
        for (int ks = 0; ks < HDIM; ks += 8) {
            unsigned af[4];
            af[0] = sQ[(mb + g    )*QW + ks + l4    ];
            af[1] = sQ[(mb + g + 8)*QW + ks + l4    ];
            af[2] = sQ[(mb + g    )*QW + ks + l4 + 4];
            af[3] = sQ[(mb + g + 8)*QW + ks + l4 + 4];
            #pragma unroll
            for (int j = 0; j < 4; j++) {
                unsigned bf[2];
                bf[0] = sK[(nbs + j*8 + g)*QW + ks + l4    ];
                bf[1] = sK[(nbs + j*8 + g)*QW + ks + l4 + 4];
                mma8(sacc[j], af, bf);
            }
        }
        const float* mrow = &mask[(size_t)b*SEQ + kt*AK];
        #pragma unroll
        for (int j = 0; j < 4; j++) {
            int col = nbs + j*8 + 2*l4;
            float m0 = mrow[col], m1 = mrow[col + 1];
            sS[(mb + g    )*SW + col    ] = sacc[j][0]*SCALE + m0;
            sS[(mb + g    )*SW + col + 1] = sacc[j][1]*SCALE + m1;
            sS[(mb + g + 8)*SW + col    ] = sacc[j][2]*SCALE + m0;
            sS[(mb + g + 8)*SW + col + 1] = sacc[j][3]*SCALE + m1;
        }
        __syncthreads();

        // Online softmax: 4 threads per row
        {
            int r = tid >> 2, q = tid & 3;
            float* row = &sS[r*SW + q*16];
            float mx = -1e30f;
            #pragma unroll
            for (int c = 0; c < 16; c++) mx = fmaxf(mx, row[c]);
            mx = fmaxf(mx, __shfl_xor_sync(0xffffffffu, mx, 1));
            mx = fmaxf(mx, __shfl_xor_sync(0xffffffffu, mx, 2));
            float m_old = sM[r];
            float mt = fmaxf(m_old, mx);
            float ls = 0.f;
            #pragma unroll
            for (int c = 0; c < 16; c++) {
                float p = __expf(row[c] - mt);
                float pr = __uint_as_float(f2tf(p));   // tf32-round P (consistent num/denom)
                ls += pr;
                row[c] = pr;
            }
            ls += __shfl_xor_sync(0xffffffffu, ls, 1);
            ls += __shfl_xor_sync(0xffffffffu, ls, 2);
            if (q == 0) {
                float f = __expf(m_old - mt);
                sM[r] = mt; sF[r] = f; sL[r] = sL[r]*f + ls;
            }
        }
        __syncthreads();

        // Rescale + O += P V
        float f0 = sF[mb + g], f1 = sF[mb + g + 8];
        #pragma unroll
        for (int j = 0; j < 8; j++) {
            oacc[j][0] *= f0; oacc[j][1] *= f0;
            oacc[j][2] *= f1; oacc[j][3] *= f1;
        }
        #pragma unroll
        for (int ks = 0; ks < AK; ks += 8) {
            unsigned af[4];
            af[0] = *(const unsigned*)&sS[(mb + g    )*SW + ks + l4    ];
            af[1] = *(const unsigned*)&sS[(mb + g + 8)*SW + ks + l4    ];
            af[2] = *(const unsigned*)&sS[(mb + g    )*SW + ks + l4 + 4];
            af[3] = *(const unsigned*)&sS[(mb + g + 8)*SW + ks + l4 + 4];
            #pragma unroll
            for (int j = 0; j < 8; j++) {
                unsigned bf[2];
                bf[0] = sV[(ks + l4    )*QW + nbo + j*8 + g];
                bf[1] = sV[(ks + l4 + 4)*QW + nbo + j*8 + g];
                mma8(oacc[j], af, bf);
            }
        }
        __syncthreads();
    }

    // Normalize and write ctx in [B*S, HIDDEN] layout
    float i0 = 1.f / sL[mb + g], i1 = 1.f / sL[mb + g + 8];
    #pragma unroll
    for (int j = 0; j < 8; j++) {
        int col = nbo + j*8 + 2*l4;
        size_t r0 = base + (size_t)(qt*AQ + mb + g    )*HIDDEN + col;
        size_t r1 = base + (size_t)(qt*AQ + mb + g + 8)*HIDDEN + col;
        float2 v0 = { oacc[j][0]*i0, oacc[j][1]*i0 };
        float2 v1 = { oacc[j][2]*i1, oacc[j][3]*i1 };
        *(float2*)&O[r0] = v0;
        *(float2*)&O[r1] = v1;
    }
}

// ---------------------------------------------------------------------------
extern "C" void kernel_launch(void* const* d_in, const int* in_sizes, int n_in,
                              void* d_out, int out_size) {
    const float* X    = (const float*)d_in[0];
    const float* mask = (const float*)d_in[1];
    const float* Wq   = (const float*)d_in[2];
    const float* bq   = (const float*)d_in[3];
    const float* Wk   = (const float*)d_in[4];
    const float* bk   = (const float*)d_in[5];
    const float* Wv   = (const float*)d_in[6];
    const float* bv   = (const float*)d_in[7];
    const float* Wo   = (const float*)d_in[8];
    const float* bo   = (const float*)d_in[9];
    float* out = (float*)d_out;

    float *qp, *kp, *vp, *cp;
    cudaGetSymbolAddress((void**)&qp, g_Q);
    cudaGetSymbolAddress((void**)&kp, g_K);
    cudaGetSymbolAddress((void**)&vp, g_V);
    cudaGetSymbolAddress((void**)&cp, g_C);

    dim3 ggrid(HIDDEN/BN, ROWS/BM);   // (16, 32)
    tf32_gemm_nt_bias<<<ggrid, 256>>>(X, Wq, bq, qp, ROWS, HIDDEN, HIDDEN);
    tf32_gemm_nt_bias<<<ggrid, 256>>>(X, Wk, bk, kp, ROWS, HIDDEN, HIDDEN);
    tf32_gemm_nt_bias<<<ggrid, 256>>>(X, Wv, bv, vp, ROWS, HIDDEN, HIDDEN);

    cudaFuncSetAttribute(attn_tf32, cudaFuncAttributeMaxDynamicSharedMemorySize,
                         (int)ATT_SMEM);
    dim3 agrid(SEQ/AQ, NHEADS, BATCH);  // (32, 16, 2)
    attn_tf32<<<agrid, 256, ATT_SMEM>>>(qp, kp, vp, mask, cp);

    tf32_gemm_nt_bias<<<ggrid, 256>>>(cp, Wo, bo, out, ROWS, HIDDEN, HIDDEN);
}

// round 5
// speedup vs baseline: 4.7264x; 1.5368x over previous
#include <cuda_runtime.h>
#include <math.h>
#include <cstdint>

#define HIDDEN 2048
#define NHEADS 16
#define HDIM   128
#define BATCH  2
#define SEQ    2048
#define ROWS   (BATCH*SEQ)             // 4096
#define SCALE  0.08838834764831845f    // 1/sqrt(128)

// Scratch (allocation-guard-safe)
__device__ float g_Q[ROWS*HIDDEN];
__device__ float g_K[ROWS*HIDDEN];
__device__ float g_V[ROWS*HIDDEN];
__device__ float g_C[ROWS*HIDDEN];
__device__ float g_Xr[ROWS*HIDDEN];          // tf32-rounded hidden_states
__device__ float g_Wr[4*HIDDEN*HIDDEN];      // tf32-rounded Wq,Wk,Wv,Wo

// ---------------------------------------------------------------------------
// Helpers
// ---------------------------------------------------------------------------
__device__ __forceinline__ unsigned f2tf(float f) {
    unsigned u; asm("cvt.rna.tf32.f32 %0, %1;" : "=r"(u) : "f"(f)); return u;
}
__device__ __forceinline__ uint32_t smem_u32(const void* p) {
    uint32_t a; asm("{ .reg .u64 t; cvta.to.shared.u64 t, %1; cvt.u32.u64 %0, t; }"
                    : "=r"(a) : "l"(p));
    return a;
}
__device__ __forceinline__ void cpa16(uint32_t dst, const void* src) {
    asm volatile("cp.async.cg.shared.global [%0], [%1], 16;" :: "r"(dst), "l"(src));
}
#define CP_COMMIT()  asm volatile("cp.async.commit_group;" ::: "memory")
#define CP_WAIT(n)   asm volatile("cp.async.wait_group %0;" :: "n"(n) : "memory")

__device__ __forceinline__ void mma8(float* c, const unsigned* a, const unsigned* b) {
    asm volatile(
        "mma.sync.aligned.m16n8k8.row.col.f32.tf32.tf32.f32 "
        "{%0,%1,%2,%3}, {%4,%5,%6,%7}, {%8,%9}, {%0,%1,%2,%3};"
        : "+f"(c[0]), "+f"(c[1]), "+f"(c[2]), "+f"(c[3])
        : "r"(a[0]), "r"(a[1]), "r"(a[2]), "r"(a[3]), "r"(b[0]), "r"(b[1]));
}

// ---------------------------------------------------------------------------
// Elementwise tf32 pre-round
// ---------------------------------------------------------------------------
__global__ void round_tf32_kernel(const float* __restrict__ in, float* __restrict__ out, int n4) {
    int i = blockIdx.x * blockDim.x + threadIdx.x;
    if (i < n4) {
        float4 v = ((const float4*)in)[i];
        float4 o;
        o.x = __uint_as_float(f2tf(v.x));
        o.y = __uint_as_float(f2tf(v.y));
        o.z = __uint_as_float(f2tf(v.z));
        o.w = __uint_as_float(f2tf(v.w));
        ((float4*)out)[i] = o;
    }
}

// ---------------------------------------------------------------------------
// TF32 mma.sync GEMM:  C[M,N] = A[M,K] @ W[N,K]^T + bias
// 128x256x32 block tile, 3-stage cp.async pipeline, 8 warps (2x4),
// warp tile 64x64 via 4x8 m16n8k8 tiles -> 1.0 LDS per HMMA.
// Inputs must be pre-rounded to tf32 bit patterns.
// ---------------------------------------------------------------------------
#define GBM 128
#define GBN 256
#define GBK 32
#define AST 36                        // smem row stride (floats), 32 + 4 pad
#define A_FLOATS (GBM*AST)            // 4608
#define B_FLOATS (GBN*AST)            // 9216
#define STG_FLOATS (A_FLOATS + B_FLOATS)   // 13824
#define NSTAGE 3
#define GEMM_SMEM (NSTAGE*STG_FLOATS*4)    // 165888 bytes
#define KCHUNKS (HIDDEN/GBK)          // 64

template<bool ROUND_OUT>
__global__ __launch_bounds__(256, 1) void tf32_gemm(
    const float* __restrict__ A, const float* __restrict__ W,
    const float* __restrict__ bias, float* __restrict__ C)
{
    extern __shared__ float sm[];
    const uint32_t sbase = smem_u32(sm);
    const int tid  = threadIdx.x;
    const int lane = tid & 31;
    const int warp = tid >> 5;
    const int g    = lane >> 2;        // 0..7
    const int l4   = lane & 3;         // 0..3
    const int mb   = (warp & 1) * 64;  // warp row block
    const int nb   = (warp >> 1) * 64; // warp col block
    const int brow = blockIdx.y * GBM;
    const int bn   = blockIdx.x * GBN;

    float acc[4][8][4];
    #pragma unroll
    for (int i = 0; i < 4; i++)
        #pragma unroll
        for (int j = 0; j < 8; j++)
            #pragma unroll
            for (int t = 0; t < 4; t++) acc[i][j][t] = 0.f;

    auto load_stage = [&](int c, int s) {
        const uint32_t dA = sbase + (uint32_t)s * (STG_FLOATS * 4);
        const uint32_t dB = dA + A_FLOATS * 4;
        const int k0 = c * GBK;
        #pragma unroll
        for (int i = 0; i < 4; i++) {            // A: 128 rows x 32 floats
            int idx = tid + i * 256;
            int row = idx >> 3, kc = (idx & 7) * 4;
            cpa16(dA + row * (AST*4) + kc * 4,
                  &A[(size_t)(brow + row) * HIDDEN + k0 + kc]);
        }
        #pragma unroll
        for (int i = 0; i < 8; i++) {            // B: 256 rows x 32 floats
            int idx = tid + i * 256;
            int row = idx >> 3, kc = (idx & 7) * 4;
            cpa16(dB + row * (AST*4) + kc * 4,
                  &W[(size_t)(bn + row) * HIDDEN + k0 + kc]);
        }
        CP_COMMIT();
    };

    load_stage(0, 0);
    load_stage(1, 1);

    int s = 0;
    for (int c = 0; c < KCHUNKS; c++) {
        if (c == KCHUNKS - 1) { CP_WAIT(0); } else { CP_WAIT(1); }
        __syncthreads();
        if (c + 2 < KCHUNKS) load_stage(c + 2, (c + 2) % NSTAGE);

        const float* pA = sm + s * STG_FLOATS + mb * AST;
        const float* pB = sm + s * STG_FLOATS + A_FLOATS + nb * AST;

        #pragma unroll
        for (int ks = 0; ks < GBK; ks += 8) {
            unsigned af[4][4], bf[8][2];
            #pragma unroll
            for (int i = 0; i < 4; i++) {
                const float* p0 = pA + (i*16 + g) * AST + ks + l4;
                af[i][0] = __float_as_uint(p0[0]);
                af[i][1] = __float_as_uint(p0[8*AST]);
                af[i][2] = __float_as_uint(p0[4]);
                af[i][3] = __float_as_uint(p0[8*AST + 4]);
            }
            #pragma unroll
            for (int j = 0; j < 8; j++) {
                const float* p0 = pB + (j*8 + g) * AST + ks + l4;
                bf[j][0] = __float_as_uint(p0[0]);
                bf[j][1] = __float_as_uint(p0[4]);
            }
            #pragma unroll
            for (int i = 0; i < 4; i++)
                #pragma unroll
                for (int j = 0; j < 8; j++)
                    mma8(acc[i][j], af[i], bf[j]);
        }
        s = (s == NSTAGE - 1) ? 0 : s + 1;
    }

    // epilogue
    #pragma unroll
    for (int i = 0; i < 4; i++) {
        const int r0 = brow + mb + i*16 + g;
        #pragma unroll
        for (int j = 0; j < 8; j++) {
            const int col = bn + nb + j*8 + 2*l4;
            float b0 = bias[col], b1 = bias[col + 1];
            float v0 = acc[i][j][0] + b0, v1 = acc[i][j][1] + b1;
            float v2 = acc[i][j][2] + b0, v3 = acc[i][j][3] + b1;
            if (ROUND_OUT) {
                v0 = __uint_as_float(f2tf(v0)); v1 = __uint_as_float(f2tf(v1));
                v2 = __uint_as_float(f2tf(v2)); v3 = __uint_as_float(f2tf(v3));
            }
            float2 w0 = {v0, v1}, w1 = {v2, v3};
            *(float2*)&C[(size_t)r0 * HIDDEN + col]       = w0;
            *(float2*)&C[(size_t)(r0 + 8) * HIDDEN + col] = w1;
        }
    }
}

// ---------------------------------------------------------------------------
// Flash attention, tf32 mma.sync. 64 q-rows per block, 128 keys per iter.
// 8 warps: (warp&1) picks 32-q half; (warp>>1) picks 32-wide key block (QK)
// or 32-wide headdim block (PV). 2.0 LDS per HMMA.
// Inputs pre-rounded tf32; output stores tf32-rounded (feeds Wo GEMM).
// ---------------------------------------------------------------------------
#define AQ  64
#define AKK 128
#define QW  132    // row stride: 128 + 4 pad
#define ATT_SMEM ((AQ*QW + 2*AKK*QW + AQ*QW + 3*AQ) * 4)   // 203520 B

__global__ __launch_bounds__(256, 1) void attn_tf32(
    const float* __restrict__ Q, const float* __restrict__ K,
    const float* __restrict__ V, const float* __restrict__ mask,
    float* __restrict__ O)
{
    extern __shared__ float sm[];
    float* sQ  = sm;                    // [64][132]
    float* sK  = sQ + AQ*QW;            // [128][132]
    float* sV  = sK + AKK*QW;           // [128][132]
    float* sS  = sV + AKK*QW;           // [64][132]
    float* sMx = sS + AQ*QW;
    float* sL  = sMx + AQ;
    float* sF  = sL + AQ;

    const int tid  = threadIdx.x;
    const int lane = tid & 31;
    const int warp = tid >> 5;
    const int g    = lane >> 2;
    const int l4   = lane & 3;
    const int mb   = (warp & 1) * 32;   // q block (rows mb..mb+31)
    const int cb   = (warp >> 1) * 32;  // key block (QK) / headdim block (PV)
    const int qt = blockIdx.x, h = blockIdx.y, b = blockIdx.z;
    const size_t base = (size_t)b * SEQ * HIDDEN + (size_t)h * HDIM;

    // resident Q tile (raw bits; already tf32-rounded)
    for (int it = tid; it < AQ*HDIM/4; it += 256) {
        int r = it >> 5, c = (it & 31) * 4;
        float4 v = *(const float4*)&Q[base + (size_t)(qt*AQ + r)*HIDDEN + c];
        *(float4*)&sQ[r*QW + c] = v;
    }
    if (tid < AQ) { sMx[tid] = -1e30f; sL[tid] = 0.f; }

    float oacc[2][4][4];
    #pragma unroll
    for (int i = 0; i < 2; i++)
        #pragma unroll
        for (int j = 0; j < 4; j++)
            #pragma unroll
            for (int t = 0; t < 4; t++) oacc[i][j][t] = 0.f;

    for (int kt = 0; kt < SEQ/AKK; kt++) {      // 16 iterations
        __syncthreads();   // prior PV done before K/V overwrite (also covers Q load at kt=0)
        for (int it = tid; it < AKK*HDIM/4; it += 256) {
            int r = it >> 5, c = (it & 31) * 4;
            size_t gi = base + (size_t)(kt*AKK + r)*HIDDEN + c;
            *(float4*)&sK[r*QW + c] = *(const float4*)&K[gi];
            *(float4*)&sV[r*QW + c] = *(const float4*)&V[gi];
        }
        __syncthreads();

        // ---- S = Q K^T on warp tile [mb:mb+32] x [cb:cb+32]
        float sacc[2][4][4];
        #pragma unroll
        for (int i = 0; i < 2; i++)
            #pragma unroll
            for (int j = 0; j < 4; j++)
                #pragma unroll
                for (int t = 0; t < 4; t++) sacc[i][j][t] = 0.f;

        #pragma unroll
        for (int ks = 0; ks < HDIM; ks += 8) {
            unsigned af[2][4], bf[4][2];
            #pragma unroll
            for (int i = 0; i < 2; i++) {
                const float* p0 = &sQ[(mb + i*16 + g)*QW + ks + l4];
                af[i][0] = __float_as_uint(p0[0]);
                af[i][1] = __float_as_uint(p0[8*QW]);
                af[i][2] = __float_as_uint(p0[4]);
                af[i][3] = __float_as_uint(p0[8*QW + 4]);
            }
            #pragma unroll
            for (int j = 0; j < 4; j++) {
                const float* p0 = &sK[(cb + j*8 + g)*QW + ks + l4];
                bf[j][0] = __float_as_uint(p0[0]);
                bf[j][1] = __float_as_uint(p0[4]);
            }
            #pragma unroll
            for (int i = 0; i < 2; i++)
                #pragma unroll
                for (int j = 0; j < 4; j++)
                    mma8(sacc[i][j], af[i], bf[j]);
        }
        const float* mrow = &mask[(size_t)b*SEQ + kt*AKK];
        #pragma unroll
        for (int i = 0; i < 2; i++) {
            #pragma unroll
            for (int j = 0; j < 4; j++) {
                int col = cb + j*8 + 2*l4;
                float m0 = mrow[col], m1 = mrow[col + 1];
                int row = (mb + i*16 + g)*QW;
                sS[row + col]          = sacc[i][j][0]*SCALE + m0;
                sS[row + col + 1]      = sacc[i][j][1]*SCALE + m1;
                sS[row + 8*QW + col]   = sacc[i][j][2]*SCALE + m0;
                sS[row + 8*QW + col+1] = sacc[i][j][3]*SCALE + m1;
            }
        }
        __syncthreads();

        // ---- online softmax: 4 threads per row, 32 cols each
        {
            int r = tid >> 2, q = tid & 3;
            float* row = &sS[r*QW + q*32];
            float mx = -1e30f;
            #pragma unroll
            for (int c = 0; c < 32; c++) mx = fmaxf(mx, row[c]);
            mx = fmaxf(mx, __shfl_xor_sync(0xffffffffu, mx, 1));
            mx = fmaxf(mx, __shfl_xor_sync(0xffffffffu, mx, 2));
            float m_old = sMx[r];
            float mt = fmaxf(m_old, mx);
            float ls = 0.f;
            #pragma unroll
            for (int c = 0; c < 32; c++) {
                float p = __expf(row[c] - mt);
                float pr = __uint_as_float(f2tf(p));   // tf32-consistent num/denom
                ls += pr;
                row[c] = pr;
            }
            ls += __shfl_xor_sync(0xffffffffu, ls, 1);
            ls += __shfl_xor_sync(0xffffffffu, ls, 2);
            if (q == 0) {
                float f = __expf(m_old - mt);
                sMx[r] = mt; sF[r] = f; sL[r] = sL[r]*f + ls;
            }
        }
        __syncthreads();

        // ---- O = f*O + P V on warp tile [mb:mb+32] x d[cb:cb+32]
        float fr0[2], fr1[2];
        #pragma unroll
        for (int i = 0; i < 2; i++) {
            fr0[i] = sF[mb + i*16 + g];
            fr1[i] = sF[mb + i*16 + g + 8];
        }
        #pragma unroll
        for (int i = 0; i < 2; i++)
            #pragma unroll
            for (int j = 0; j < 4; j++) {
                oacc[i][j][0] *= fr0[i]; oacc[i][j][1] *= fr0[i];
                oacc[i][j][2] *= fr1[i]; oacc[i][j][3] *= fr1[i];
            }
        #pragma unroll
        for (int ks = 0; ks < AKK; ks += 8) {
            unsigned af[2][4], bf[4][2];
            #pragma unroll
            for (int i = 0; i < 2; i++) {
                const float* p0 = &sS[(mb + i*16 + g)*QW + ks + l4];
                af[i][0] = __float_as_uint(p0[0]);
                af[i][1] = __float_as_uint(p0[8*QW]);
                af[i][2] = __float_as_uint(p0[4]);
                af[i][3] = __float_as_uint(p0[8*QW + 4]);
            }
            #pragma unroll
            for (int j = 0; j < 4; j++) {
                const float* p0 = &sV[(ks + l4)*QW + cb + j*8 + g];
                bf[j][0] = __float_as_uint(p0[0]);
                bf[j][1] = __float_as_uint(p0[4*QW]);
            }
            #pragma unroll
            for (int i = 0; i < 2; i++)
                #pragma unroll
                for (int j = 0; j < 4; j++)
                    mma8(oacc[i][j], af[i], bf[j]);
        }
    }

    // final normalize + write (tf32-rounded so Wo GEMM's A is pre-rounded)
    #pragma unroll
    for (int i = 0; i < 2; i++) {
        float i0 = 1.f / sL[mb + i*16 + g];
        float i1 = 1.f / sL[mb + i*16 + g + 8];
        #pragma unroll
        for (int j = 0; j < 4; j++) {
            int col = cb + j*8 + 2*l4;
            size_t r0 = base + (size_t)(qt*AQ + mb + i*16 + g    )*HIDDEN + col;
            size_t r1 = base + (size_t)(qt*AQ + mb + i*16 + g + 8)*HIDDEN + col;
            float2 v0 = { __uint_as_float(f2tf(oacc[i][j][0]*i0)),
                          __uint_as_float(f2tf(oacc[i][j][1]*i0)) };
            float2 v1 = { __uint_as_float(f2tf(oacc[i][j][2]*i1)),
                          __uint_as_float(f2tf(oacc[i][j][3]*i1)) };
            *(float2*)&O[r0] = v0;
            *(float2*)&O[r1] = v1;
        }
    }
}

// ---------------------------------------------------------------------------
extern "C" void kernel_launch(void* const* d_in, const int* in_sizes, int n_in,
                              void* d_out, int out_size) {
    const float* X    = (const float*)d_in[0];
    const float* mask = (const float*)d_in[1];
    const float* Wq   = (const float*)d_in[2];
    const float* bq   = (const float*)d_in[3];
    const float* Wk   = (const float*)d_in[4];
    const float* bk   = (const float*)d_in[5];
    const float* Wv   = (const float*)d_in[6];
    const float* bv   = (const float*)d_in[7];
    const float* Wo   = (const float*)d_in[8];
    const float* bo   = (const float*)d_in[9];
    float* out = (float*)d_out;

    float *qp, *kp, *vp, *cp, *xr, *wr;
    cudaGetSymbolAddress((void**)&qp, g_Q);
    cudaGetSymbolAddress((void**)&kp, g_K);
    cudaGetSymbolAddress((void**)&vp, g_V);
    cudaGetSymbolAddress((void**)&cp, g_C);
    cudaGetSymbolAddress((void**)&xr, g_Xr);
    cudaGetSymbolAddress((void**)&wr, g_Wr);

    // tf32 pre-round (X and the four weight matrices)
    const int NX4 = ROWS*HIDDEN/4, NW4 = HIDDEN*HIDDEN/4;
    round_tf32_kernel<<<(NX4+255)/256, 256>>>(X,  xr, NX4);
    round_tf32_kernel<<<(NW4+255)/256, 256>>>(Wq, wr + 0*HIDDEN*HIDDEN, NW4);
    round_tf32_kernel<<<(NW4+255)/256, 256>>>(Wk, wr + 1*HIDDEN*HIDDEN, NW4);
    round_tf32_kernel<<<(NW4+255)/256, 256>>>(Wv, wr + 2*HIDDEN*HIDDEN, NW4);
    round_tf32_kernel<<<(NW4+255)/256, 256>>>(Wo, wr + 3*HIDDEN*HIDDEN, NW4);

    cudaFuncSetAttribute(tf32_gemm<true>,  cudaFuncAttributeMaxDynamicSharedMemorySize, GEMM_SMEM);
    cudaFuncSetAttribute(tf32_gemm<false>, cudaFuncAttributeMaxDynamicSharedMemorySize, GEMM_SMEM);

    dim3 ggrid(HIDDEN/GBN, ROWS/GBM);   // (8, 32)
    tf32_gemm<true><<<ggrid, 256, GEMM_SMEM>>>(xr, wr + 0*HIDDEN*HIDDEN, bq, qp);
    tf32_gemm<true><<<ggrid, 256, GEMM_SMEM>>>(xr, wr + 1*HIDDEN*HIDDEN, bk, kp);
    tf32_gemm<true><<<ggrid, 256, GEMM_SMEM>>>(xr, wr + 2*HIDDEN*HIDDEN, bv, vp);

    cudaFuncSetAttribute(attn_tf32, cudaFuncAttributeMaxDynamicSharedMemorySize, (int)ATT_SMEM);
    dim3 agrid(SEQ/AQ, NHEADS, BATCH);  // (32, 16, 2)
    attn_tf32<<<agrid, 256, ATT_SMEM>>>(qp, kp, vp, mask, cp);

    tf32_gemm<false><<<ggrid, 256, GEMM_SMEM>>>(cp, wr + 3*HIDDEN*HIDDEN, bo, out);
}

// round 6
// speedup vs baseline: 5.4803x; 1.1595x over previous
#include <cuda_runtime.h>
#include <math.h>
#include <cstdint>

#define HIDDEN 2048
#define NHEADS 16
#define HDIM   128
#define BATCH  2
#define SEQ    2048
#define ROWS   (BATCH*SEQ)             // 4096
#define SCALE  0.08838834764831845f    // 1/sqrt(128)
#define SCALE2 0.12752041986642899f    // SCALE * log2(e)
#define LOG2E  1.4426950408889634f

// Scratch (allocation-guard-safe)
__device__ float g_Q[ROWS*HIDDEN];
__device__ float g_K[ROWS*HIDDEN];
__device__ float g_V[ROWS*HIDDEN];
__device__ float g_C[ROWS*HIDDEN];
__device__ float g_Xr[ROWS*HIDDEN];          // tf32-rounded hidden_states
__device__ float g_Wr[4*HIDDEN*HIDDEN];      // tf32-rounded Wq,Wk,Wv,Wo

// ---------------------------------------------------------------------------
// Helpers
// ---------------------------------------------------------------------------
__device__ __forceinline__ unsigned f2tf(float f) {
    unsigned u; asm("cvt.rna.tf32.f32 %0, %1;" : "=r"(u) : "f"(f)); return u;
}
__device__ __forceinline__ float ex2(float x) {
    float r; asm("ex2.approx.f32 %0, %1;" : "=f"(r) : "f"(x)); return r;
}
__device__ __forceinline__ uint32_t smem_u32(const void* p) {
    uint32_t a; asm("{ .reg .u64 t; cvta.to.shared.u64 t, %1; cvt.u32.u64 %0, t; }"
                    : "=r"(a) : "l"(p));
    return a;
}
__device__ __forceinline__ void cpa16(uint32_t dst, const void* src) {
    asm volatile("cp.async.cg.shared.global [%0], [%1], 16;" :: "r"(dst), "l"(src));
}
#define CP_COMMIT()  asm volatile("cp.async.commit_group;" ::: "memory")
#define CP_WAIT(n)   asm volatile("cp.async.wait_group %0;" :: "n"(n) : "memory")

__device__ __forceinline__ void mma8(float* c, const unsigned* a, const unsigned* b) {
    asm volatile(
        "mma.sync.aligned.m16n8k8.row.col.f32.tf32.tf32.f32 "
        "{%0,%1,%2,%3}, {%4,%5,%6,%7}, {%8,%9}, {%0,%1,%2,%3};"
        : "+f"(c[0]), "+f"(c[1]), "+f"(c[2]), "+f"(c[3])
        : "r"(a[0]), "r"(a[1]), "r"(a[2]), "r"(a[3]), "r"(b[0]), "r"(b[1]));
}

// ---------------------------------------------------------------------------
// Elementwise tf32 pre-round
// ---------------------------------------------------------------------------
__global__ void round_tf32_kernel(const float* __restrict__ in, float* __restrict__ out, int n4) {
    int i = blockIdx.x * blockDim.x + threadIdx.x;
    if (i < n4) {
        float4 v = ((const float4*)in)[i];
        float4 o;
        o.x = __uint_as_float(f2tf(v.x));
        o.y = __uint_as_float(f2tf(v.y));
        o.z = __uint_as_float(f2tf(v.z));
        o.w = __uint_as_float(f2tf(v.w));
        ((float4*)out)[i] = o;
    }
}

// ---------------------------------------------------------------------------
// TF32 mma.sync GEMM:  C[M,N] = A[M,K] @ W[N,K]^T + bias   (unchanged, proven)
// ---------------------------------------------------------------------------
#define GBM 128
#define GBN 256
#define GBK 32
#define AST 36
#define A_FLOATS (GBM*AST)
#define B_FLOATS (GBN*AST)
#define STG_FLOATS (A_FLOATS + B_FLOATS)
#define NSTAGE 3
#define GEMM_SMEM (NSTAGE*STG_FLOATS*4)
#define KCHUNKS (HIDDEN/GBK)

template<bool ROUND_OUT>
__global__ __launch_bounds__(256, 1) void tf32_gemm(
    const float* __restrict__ A, const float* __restrict__ W,
    const float* __restrict__ bias, float* __restrict__ C)
{
    extern __shared__ float sm[];
    const uint32_t sbase = smem_u32(sm);
    const int tid  = threadIdx.x;
    const int lane = tid & 31;
    const int warp = tid >> 5;
    const int g    = lane >> 2;
    const int l4   = lane & 3;
    const int mb   = (warp & 1) * 64;
    const int nb   = (warp >> 1) * 64;
    const int brow = blockIdx.y * GBM;
    const int bn   = blockIdx.x * GBN;

    float acc[4][8][4];
    #pragma unroll
    for (int i = 0; i < 4; i++)
        #pragma unroll
        for (int j = 0; j < 8; j++)
            #pragma unroll
            for (int t = 0; t < 4; t++) acc[i][j][t] = 0.f;

    auto load_stage = [&](int c, int s) {
        const uint32_t dA = sbase + (uint32_t)s * (STG_FLOATS * 4);
        const uint32_t dB = dA + A_FLOATS * 4;
        const int k0 = c * GBK;
        #pragma unroll
        for (int i = 0; i < 4; i++) {
            int idx = tid + i * 256;
            int row = idx >> 3, kc = (idx & 7) * 4;
            cpa16(dA + row * (AST*4) + kc * 4,
                  &A[(size_t)(brow + row) * HIDDEN + k0 + kc]);
        }
        #pragma unroll
        for (int i = 0; i < 8; i++) {
            int idx = tid + i * 256;
            int row = idx >> 3, kc = (idx & 7) * 4;
            cpa16(dB + row * (AST*4) + kc * 4,
                  &W[(size_t)(bn + row) * HIDDEN + k0 + kc]);
        }
        CP_COMMIT();
    };

    load_stage(0, 0);
    load_stage(1, 1);

    int s = 0;
    for (int c = 0; c < KCHUNKS; c++) {
        if (c == KCHUNKS - 1) { CP_WAIT(0); } else { CP_WAIT(1); }
        __syncthreads();
        if (c + 2 < KCHUNKS) load_stage(c + 2, (c + 2) % NSTAGE);

        const float* pA = sm + s * STG_FLOATS + mb * AST;
        const float* pB = sm + s * STG_FLOATS + A_FLOATS + nb * AST;

        #pragma unroll
        for (int ks = 0; ks < GBK; ks += 8) {
            unsigned af[4][4], bf[8][2];
            #pragma unroll
            for (int i = 0; i < 4; i++) {
                const float* p0 = pA + (i*16 + g) * AST + ks + l4;
                af[i][0] = __float_as_uint(p0[0]);
                af[i][1] = __float_as_uint(p0[8*AST]);
                af[i][2] = __float_as_uint(p0[4]);
                af[i][3] = __float_as_uint(p0[8*AST + 4]);
            }
            #pragma unroll
            for (int j = 0; j < 8; j++) {
                const float* p0 = pB + (j*8 + g) * AST + ks + l4;
                bf[j][0] = __float_as_uint(p0[0]);
                bf[j][1] = __float_as_uint(p0[4]);
            }
            #pragma unroll
            for (int i = 0; i < 4; i++)
                #pragma unroll
                for (int j = 0; j < 8; j++)
                    mma8(acc[i][j], af[i], bf[j]);
        }
        s = (s == NSTAGE - 1) ? 0 : s + 1;
    }

    #pragma unroll
    for (int i = 0; i < 4; i++) {
        const int r0 = brow + mb + i*16 + g;
        #pragma unroll
        for (int j = 0; j < 8; j++) {
            const int col = bn + nb + j*8 + 2*l4;
            float b0 = bias[col], b1 = bias[col + 1];
            float v0 = acc[i][j][0] + b0, v1 = acc[i][j][1] + b1;
            float v2 = acc[i][j][2] + b0, v3 = acc[i][j][3] + b1;
            if (ROUND_OUT) {
                v0 = __uint_as_float(f2tf(v0)); v1 = __uint_as_float(f2tf(v1));
                v2 = __uint_as_float(f2tf(v2)); v3 = __uint_as_float(f2tf(v3));
            }
            float2 w0 = {v0, v1}, w1 = {v2, v3};
            *(float2*)&C[(size_t)r0 * HIDDEN + col]       = w0;
            *(float2*)&C[(size_t)(r0 + 8) * HIDDEN + col] = w1;
        }
    }
}

// ---------------------------------------------------------------------------
// Flash attention, tf32 mma.sync, register-resident log2-domain softmax.
// 64 q-rows per block, 128 keys per iter, 8 warps:
//   mb=(warp&1)*32 picks q half; wc=warp>>1 picks 32-wide key block (QK)
//   or 32-wide headdim block (PV).
// cp.async: K committed first, V second -> wait_group(1) gates QK on K only;
// V load overlaps QK+softmax.
// ---------------------------------------------------------------------------
#define AQ  64
#define AKK 128
#define QW  132    // row stride (floats): 128 + 4 pad
// smem float offsets
#define OQ  0
#define OK  (AQ*QW)                 // 8448
#define OV  (OK + AKK*QW)           // 25344
#define OS  (OV + AKK*QW)           // 42240
#define OMX (OS + AQ*QW)            // 50688
#define OL  (OMX + AQ)              // 50752
#define OPM (OL + AQ)               // 50816  pmax[4][64]
#define OPS (OPM + 256)             // 51072  psum[4][64]
#define ATT_FLOATS (OPS + 256)      // 51328
#define ATT_SMEM (ATT_FLOATS * 4)   // 205312 bytes

__global__ __launch_bounds__(256, 1) void attn_tf32(
    const float* __restrict__ Q, const float* __restrict__ K,
    const float* __restrict__ V, const float* __restrict__ mask,
    float* __restrict__ O)
{
    extern __shared__ float sm[];
    const uint32_t sbase = smem_u32(sm);
    float* sQ  = sm + OQ;
    float* sK  = sm + OK;
    float* sV  = sm + OV;
    float* sS  = sm + OS;
    float* sMx = sm + OMX;
    float* sL  = sm + OL;
    float* pmax = sm + OPM;
    float* psum = sm + OPS;

    const int tid  = threadIdx.x;
    const int lane = tid & 31;
    const int warp = tid >> 5;
    const int g    = lane >> 2;
    const int l4   = lane & 3;
    const int mb   = (warp & 1) * 32;
    const int wc   = warp >> 1;
    const int cb   = wc * 32;
    const int qt = blockIdx.x, h = blockIdx.y, b = blockIdx.z;
    const size_t base = (size_t)b * SEQ * HIDDEN + (size_t)h * HDIM;

    // resident Q tile (already tf32-rounded bits)
    for (int it = tid; it < AQ*HDIM/4; it += 256) {
        int r = it >> 5, c = (it & 31) * 4;
        *(float4*)&sQ[r*QW + c] =
            *(const float4*)&Q[base + (size_t)(qt*AQ + r)*HIDDEN + c];
    }
    if (tid < AQ) { sMx[tid] = -1e30f; sL[tid] = 0.f; }

    float oacc[2][4][4];
    #pragma unroll
    for (int i = 0; i < 2; i++)
        #pragma unroll
        for (int j = 0; j < 4; j++)
            #pragma unroll
            for (int t = 0; t < 4; t++) oacc[i][j][t] = 0.f;

    for (int kt = 0; kt < SEQ/AKK; kt++) {      // 16 iterations
        __syncthreads();   // (1) prior PV done: K/V/P buffers + partials free

        // issue K loads (group 1), then V loads (group 2)
        {
            const uint32_t kdst = sbase + OK*4;
            const uint32_t vdst = sbase + OV*4;
            #pragma unroll
            for (int i = 0; i < 16; i++) {
                int it = tid + i*256;
                int r = it >> 5, c = (it & 31) * 4;
                cpa16(kdst + (r*QW + c)*4,
                      &K[base + (size_t)(kt*AKK + r)*HIDDEN + c]);
            }
            CP_COMMIT();
            #pragma unroll
            for (int i = 0; i < 16; i++) {
                int it = tid + i*256;
                int r = it >> 5, c = (it & 31) * 4;
                cpa16(vdst + (r*QW + c)*4,
                      &V[base + (size_t)(kt*AKK + r)*HIDDEN + c]);
            }
            CP_COMMIT();
        }

        // mask values for this tile (log2 domain), overlap with K load
        float ml[4][2];
        {
            const float* mrow = &mask[(size_t)b*SEQ + kt*AKK];
            #pragma unroll
            for (int j = 0; j < 4; j++) {
                float2 mv = *(const float2*)&mrow[cb + j*8 + 2*l4];
                ml[j][0] = mv.x * LOG2E;
                ml[j][1] = mv.y * LOG2E;
            }
        }

        CP_WAIT(1);        // K arrived (V may still be in flight)
        __syncthreads();   // (2) K visible to all warps

        // ---- S = Q K^T on warp tile [mb:mb+32] x [cb:cb+32]
        float sacc[2][4][4];
        #pragma unroll
        for (int i = 0; i < 2; i++)
            #pragma unroll
            for (int j = 0; j < 4; j++)
                #pragma unroll
                for (int t = 0; t < 4; t++) sacc[i][j][t] = 0.f;

        #pragma unroll
        for (int ks = 0; ks < HDIM; ks += 8) {
            unsigned af[2][4], bf[4][2];
            #pragma unroll
            for (int i = 0; i < 2; i++) {
                const float* p0 = &sQ[(mb + i*16 + g)*QW + ks + l4];
                af[i][0] = __float_as_uint(p0[0]);
                af[i][1] = __float_as_uint(p0[8*QW]);
                af[i][2] = __float_as_uint(p0[4]);
                af[i][3] = __float_as_uint(p0[8*QW + 4]);
            }
            #pragma unroll
            for (int j = 0; j < 4; j++) {
                const float* p0 = &sK[(cb + j*8 + g)*QW + ks + l4];
                bf[j][0] = __float_as_uint(p0[0]);
                bf[j][1] = __float_as_uint(p0[4]);
            }
            #pragma unroll
            for (int i = 0; i < 2; i++)
                #pragma unroll
                for (int j = 0; j < 4; j++)
                    mma8(sacc[i][j], af[i], bf[j]);
        }

        // scale + mask in log2 domain (registers)
        #pragma unroll
        for (int i = 0; i < 2; i++)
            #pragma unroll
            for (int j = 0; j < 4; j++) {
                sacc[i][j][0] = sacc[i][j][0]*SCALE2 + ml[j][0];
                sacc[i][j][1] = sacc[i][j][1]*SCALE2 + ml[j][1];
                sacc[i][j][2] = sacc[i][j][2]*SCALE2 + ml[j][0];
                sacc[i][j][3] = sacc[i][j][3]*SCALE2 + ml[j][1];
            }

        // ---- per-row max partials (registers + quad shuffles)
        float mloc[2][2];
        #pragma unroll
        for (int i = 0; i < 2; i++)
            #pragma unroll
            for (int p = 0; p < 2; p++) {
                float m = -1e30f;
                #pragma unroll
                for (int j = 0; j < 4; j++)
                    m = fmaxf(m, fmaxf(sacc[i][j][2*p], sacc[i][j][2*p+1]));
                m = fmaxf(m, __shfl_xor_sync(0xffffffffu, m, 1));
                m = fmaxf(m, __shfl_xor_sync(0xffffffffu, m, 2));
                mloc[i][p] = m;
            }
        if (l4 == 0) {
            #pragma unroll
            for (int i = 0; i < 2; i++)
                #pragma unroll
                for (int p = 0; p < 2; p++)
                    pmax[wc*64 + mb + i*16 + p*8 + g] = mloc[i][p];
        }
        __syncthreads();   // (3) pmax visible

        // ---- combine maxes, exponentiate in registers, store P, sum partials
        float mtv[2][2], fv[2][2], lsum[2][2];
        #pragma unroll
        for (int i = 0; i < 2; i++)
            #pragma unroll
            for (int p = 0; p < 2; p++) {
                int r = mb + i*16 + p*8 + g;
                float mo = sMx[r];
                float mt = fmaxf(fmaxf(pmax[r], pmax[64+r]),
                                 fmaxf(pmax[128+r], pmax[192+r]));
                mt = fmaxf(mo, mt);
                mtv[i][p] = mt;
                fv[i][p]  = ex2(mo - mt);
                lsum[i][p] = 0.f;
            }
        #pragma unroll
        for (int i = 0; i < 2; i++)
            #pragma unroll
            for (int j = 0; j < 4; j++)
                #pragma unroll
                for (int p = 0; p < 2; p++) {
                    float p0 = __uint_as_float(f2tf(ex2(sacc[i][j][2*p]   - mtv[i][p])));
                    float p1 = __uint_as_float(f2tf(ex2(sacc[i][j][2*p+1] - mtv[i][p])));
                    lsum[i][p] += p0 + p1;
                    float2 pv = {p0, p1};
                    *(float2*)&sS[(mb + i*16 + p*8 + g)*QW + cb + j*8 + 2*l4] = pv;
                }
        #pragma unroll
        for (int i = 0; i < 2; i++)
            #pragma unroll
            for (int p = 0; p < 2; p++) {
                float l = lsum[i][p];
                l += __shfl_xor_sync(0xffffffffu, l, 1);
                l += __shfl_xor_sync(0xffffffffu, l, 2);
                lsum[i][p] = l;
            }
        if (l4 == 0) {
            #pragma unroll
            for (int i = 0; i < 2; i++)
                #pragma unroll
                for (int p = 0; p < 2; p++)
                    psum[wc*64 + mb + i*16 + p*8 + g] = lsum[i][p];
        }

        CP_WAIT(0);        // V arrived (own thread)
        __syncthreads();   // (4) psum + P + V visible

        // owner updates running stats (read next iter after 2 more syncs)
        if (wc == 0 && l4 == 0) {
            #pragma unroll
            for (int i = 0; i < 2; i++)
                #pragma unroll
                for (int p = 0; p < 2; p++) {
                    int r = mb + i*16 + p*8 + g;
                    float ls = psum[r] + psum[64+r] + psum[128+r] + psum[192+r];
                    sL[r]  = sL[r]*fv[i][p] + ls;
                    sMx[r] = mtv[i][p];
                }
        }

        // rescale O and accumulate P V
        #pragma unroll
        for (int i = 0; i < 2; i++)
            #pragma unroll
            for (int j = 0; j < 4; j++) {
                oacc[i][j][0] *= fv[i][0]; oacc[i][j][1] *= fv[i][0];
                oacc[i][j][2] *= fv[i][1]; oacc[i][j][3] *= fv[i][1];
            }
        #pragma unroll
        for (int ks = 0; ks < AKK; ks += 8) {
            unsigned af[2][4], bf[4][2];
            #pragma unroll
            for (int i = 0; i < 2; i++) {
                const float* p0 = &sS[(mb + i*16 + g)*QW + ks + l4];
                af[i][0] = __float_as_uint(p0[0]);
                af[i][1] = __float_as_uint(p0[8*QW]);
                af[i][2] = __float_as_uint(p0[4]);
                af[i][3] = __float_as_uint(p0[8*QW + 4]);
            }
            #pragma unroll
            for (int j = 0; j < 4; j++) {
                const float* p0 = &sV[(ks + l4)*QW + cb + j*8 + g];
                bf[j][0] = __float_as_uint(p0[0]);
                bf[j][1] = __float_as_uint(p0[4*QW]);
            }
            #pragma unroll
            for (int i = 0; i < 2; i++)
                #pragma unroll
                for (int j = 0; j < 4; j++)
                    mma8(oacc[i][j], af[i], bf[j]);
        }
    }

    __syncthreads();       // final sL updates visible

    // normalize + write (tf32-rounded so Wo GEMM's A is pre-rounded)
    #pragma unroll
    for (int i = 0; i < 2; i++) {
        float i0 = 1.f / sL[mb + i*16 + g];
        float i1 = 1.f / sL[mb + i*16 + g + 8];
        #pragma unroll
        for (int j = 0; j < 4; j++) {
            int col = cb + j*8 + 2*l4;
            size_t r0 = base + (size_t)(qt*AQ + mb + i*16 + g    )*HIDDEN + col;
            size_t r1 = base + (size_t)(qt*AQ + mb + i*16 + g + 8)*HIDDEN + col;
            float2 v0 = { __uint_as_float(f2tf(oacc[i][j][0]*i0)),
                          __uint_as_float(f2tf(oacc[i][j][1]*i0)) };
            float2 v1 = { __uint_as_float(f2tf(oacc[i][j][2]*i1)),
                          __uint_as_float(f2tf(oacc[i][j][3]*i1)) };
            *(float2*)&O[r0] = v0;
            *(float2*)&O[r1] = v1;
        }
    }
}

// ---------------------------------------------------------------------------
extern "C" void kernel_launch(void* const* d_in, const int* in_sizes, int n_in,
                              void* d_out, int out_size) {
    const float* X    = (const float*)d_in[0];
    const float* mask = (const float*)d_in[1];
    const float* Wq   = (const float*)d_in[2];
    const float* bq   = (const float*)d_in[3];
    const float* Wk   = (const float*)d_in[4];
    const float* bk   = (const float*)d_in[5];
    const float* Wv   = (const float*)d_in[6];
    const float* bv   = (const float*)d_in[7];
    const float* Wo   = (const float*)d_in[8];
    const float* bo   = (const float*)d_in[9];
    float* out = (float*)d_out;

    float *qp, *kp, *vp, *cp, *xr, *wr;
    cudaGetSymbolAddress((void**)&qp, g_Q);
    cudaGetSymbolAddress((void**)&kp, g_K);
    cudaGetSymbolAddress((void**)&vp, g_V);
    cudaGetSymbolAddress((void**)&cp, g_C);
    cudaGetSymbolAddress((void**)&xr, g_Xr);
    cudaGetSymbolAddress((void**)&wr, g_Wr);

    const int NX4 = ROWS*HIDDEN/4, NW4 = HIDDEN*HIDDEN/4;
    round_tf32_kernel<<<(NX4+255)/256, 256>>>(X,  xr, NX4);
    round_tf32_kernel<<<(NW4+255)/256, 256>>>(Wq, wr + 0*HIDDEN*HIDDEN, NW4);
    round_tf32_kernel<<<(NW4+255)/256, 256>>>(Wk, wr + 1*HIDDEN*HIDDEN, NW4);
    round_tf32_kernel<<<(NW4+255)/256, 256>>>(Wv, wr + 2*HIDDEN*HIDDEN, NW4);
    round_tf32_kernel<<<(NW4+255)/256, 256>>>(Wo, wr + 3*HIDDEN*HIDDEN, NW4);

    cudaFuncSetAttribute(tf32_gemm<true>,  cudaFuncAttributeMaxDynamicSharedMemorySize, GEMM_SMEM);
    cudaFuncSetAttribute(tf32_gemm<false>, cudaFuncAttributeMaxDynamicSharedMemorySize, GEMM_SMEM);

    dim3 ggrid(HIDDEN/GBN, ROWS/GBM);   // (8, 32)
    tf32_gemm<true><<<ggrid, 256, GEMM_SMEM>>>(xr, wr + 0*HIDDEN*HIDDEN, bq, qp);
    tf32_gemm<true><<<ggrid, 256, GEMM_SMEM>>>(xr, wr + 1*HIDDEN*HIDDEN, bk, kp);
    tf32_gemm<true><<<ggrid, 256, GEMM_SMEM>>>(xr, wr + 2*HIDDEN*HIDDEN, bv, vp);

    cudaFuncSetAttribute(attn_tf32, cudaFuncAttributeMaxDynamicSharedMemorySize, (int)ATT_SMEM);
    dim3 agrid(SEQ/AQ, NHEADS, BATCH);  // (32, 16, 2)
    attn_tf32<<<agrid, 256, ATT_SMEM>>>(qp, kp, vp, mask, cp);

    tf32_gemm<false><<<ggrid, 256, GEMM_SMEM>>>(cp, wr + 3*HIDDEN*HIDDEN, bo, out);
}

// round 7
// speedup vs baseline: 5.5705x; 1.0165x over previous
#include <cuda_runtime.h>
#include <math.h>
#include <cstdint>

#define HIDDEN 2048
#define NHEADS 16
#define HDIM   128
#define BATCH  2
#define SEQ    2048
#define ROWS   (BATCH*SEQ)             // 4096
#define SCALE  0.08838834764831845f    // 1/sqrt(128)
#define SCALE2 0.12752041986642899f    // SCALE * log2(e)
#define LOG2E  1.4426950408889634f

// Scratch (allocation-guard-safe)
__device__ float g_Q[ROWS*HIDDEN];
__device__ float g_K[ROWS*HIDDEN];
__device__ float g_V[ROWS*HIDDEN];
__device__ float g_C[ROWS*HIDDEN];
__device__ float g_Xr[ROWS*HIDDEN];          // tf32-rounded hidden_states
__device__ float g_Wr[4*HIDDEN*HIDDEN];      // tf32-rounded Wq,Wk,Wv,Wo

// ---------------------------------------------------------------------------
// Helpers
// ---------------------------------------------------------------------------
__device__ __forceinline__ unsigned f2tf(float f) {
    unsigned u; asm("cvt.rna.tf32.f32 %0, %1;" : "=r"(u) : "f"(f)); return u;
}
__device__ __forceinline__ float ex2(float x) {
    float r; asm("ex2.approx.f32 %0, %1;" : "=f"(r) : "f"(x)); return r;
}
__device__ __forceinline__ uint32_t smem_u32(const void* p) {
    uint32_t a; asm("{ .reg .u64 t; cvta.to.shared.u64 t, %1; cvt.u32.u64 %0, t; }"
                    : "=r"(a) : "l"(p));
    return a;
}
__device__ __forceinline__ void cpa16(uint32_t dst, const void* src) {
    asm volatile("cp.async.cg.shared.global [%0], [%1], 16;" :: "r"(dst), "l"(src));
}
#define CP_COMMIT()  asm volatile("cp.async.commit_group;" ::: "memory")
#define CP_WAIT(n)   asm volatile("cp.async.wait_group %0;" :: "n"(n) : "memory")

__device__ __forceinline__ void mma8(float* c, const unsigned* a, const unsigned* b) {
    asm volatile(
        "mma.sync.aligned.m16n8k8.row.col.f32.tf32.tf32.f32 "
        "{%0,%1,%2,%3}, {%4,%5,%6,%7}, {%8,%9}, {%0,%1,%2,%3};"
        : "+f"(c[0]), "+f"(c[1]), "+f"(c[2]), "+f"(c[3])
        : "r"(a[0]), "r"(a[1]), "r"(a[2]), "r"(a[3]), "r"(b[0]), "r"(b[1]));
}

// ---------------------------------------------------------------------------
// Elementwise tf32 pre-round
// ---------------------------------------------------------------------------
__global__ void round_tf32_kernel(const float* __restrict__ in, float* __restrict__ out, int n4) {
    int i = blockIdx.x * blockDim.x + threadIdx.x;
    if (i < n4) {
        float4 v = ((const float4*)in)[i];
        float4 o;
        o.x = __uint_as_float(f2tf(v.x));
        o.y = __uint_as_float(f2tf(v.y));
        o.z = __uint_as_float(f2tf(v.z));
        o.w = __uint_as_float(f2tf(v.w));
        ((float4*)out)[i] = o;
    }
}

struct WPtrs { const float* w[4]; };

__global__ void round_w4_kernel(WPtrs ws, float* __restrict__ out, int nw4) {
    int i = blockIdx.x * blockDim.x + threadIdx.x;   // over 4*nw4
    int which = i / nw4;
    int off   = i - which * nw4;
    float4 v = ((const float4*)ws.w[which])[off];
    float4 o;
    o.x = __uint_as_float(f2tf(v.x));
    o.y = __uint_as_float(f2tf(v.y));
    o.z = __uint_as_float(f2tf(v.z));
    o.w = __uint_as_float(f2tf(v.w));
    ((float4*)out)[i] = o;
}

// ---------------------------------------------------------------------------
// TF32 mma.sync GEMM:  C[M,N] = A[M,K] @ W[N,K]^T + bias   (unchanged, proven)
// ---------------------------------------------------------------------------
#define GBM 128
#define GBN 256
#define GBK 32
#define AST 36
#define A_FLOATS (GBM*AST)
#define B_FLOATS (GBN*AST)
#define STG_FLOATS (A_FLOATS + B_FLOATS)
#define NSTAGE 3
#define GEMM_SMEM (NSTAGE*STG_FLOATS*4)
#define KCHUNKS (HIDDEN/GBK)

template<bool ROUND_OUT>
__global__ __launch_bounds__(256, 1) void tf32_gemm(
    const float* __restrict__ A, const float* __restrict__ W,
    const float* __restrict__ bias, float* __restrict__ C)
{
    extern __shared__ float sm[];
    const uint32_t sbase = smem_u32(sm);
    const int tid  = threadIdx.x;
    const int lane = tid & 31;
    const int warp = tid >> 5;
    const int g    = lane >> 2;
    const int l4   = lane & 3;
    const int mb   = (warp & 1) * 64;
    const int nb   = (warp >> 1) * 64;
    const int brow = blockIdx.y * GBM;
    const int bn   = blockIdx.x * GBN;

    float acc[4][8][4];
    #pragma unroll
    for (int i = 0; i < 4; i++)
        #pragma unroll
        for (int j = 0; j < 8; j++)
            #pragma unroll
            for (int t = 0; t < 4; t++) acc[i][j][t] = 0.f;

    auto load_stage = [&](int c, int s) {
        const uint32_t dA = sbase + (uint32_t)s * (STG_FLOATS * 4);
        const uint32_t dB = dA + A_FLOATS * 4;
        const int k0 = c * GBK;
        #pragma unroll
        for (int i = 0; i < 4; i++) {
            int idx = tid + i * 256;
            int row = idx >> 3, kc = (idx & 7) * 4;
            cpa16(dA + row * (AST*4) + kc * 4,
                  &A[(size_t)(brow + row) * HIDDEN + k0 + kc]);
        }
        #pragma unroll
        for (int i = 0; i < 8; i++) {
            int idx = tid + i * 256;
            int row = idx >> 3, kc = (idx & 7) * 4;
            cpa16(dB + row * (AST*4) + kc * 4,
                  &W[(size_t)(bn + row) * HIDDEN + k0 + kc]);
        }
        CP_COMMIT();
    };

    load_stage(0, 0);
    load_stage(1, 1);

    int s = 0;
    for (int c = 0; c < KCHUNKS; c++) {
        if (c == KCHUNKS - 1) { CP_WAIT(0); } else { CP_WAIT(1); }
        __syncthreads();
        if (c + 2 < KCHUNKS) load_stage(c + 2, (c + 2) % NSTAGE);

        const float* pA = sm + s * STG_FLOATS + mb * AST;
        const float* pB = sm + s * STG_FLOATS + A_FLOATS + nb * AST;

        #pragma unroll
        for (int ks = 0; ks < GBK; ks += 8) {
            unsigned af[4][4], bf[8][2];
            #pragma unroll
            for (int i = 0; i < 4; i++) {
                const float* p0 = pA + (i*16 + g) * AST + ks + l4;
                af[i][0] = __float_as_uint(p0[0]);
                af[i][1] = __float_as_uint(p0[8*AST]);
                af[i][2] = __float_as_uint(p0[4]);
                af[i][3] = __float_as_uint(p0[8*AST + 4]);
            }
            #pragma unroll
            for (int j = 0; j < 8; j++) {
                const float* p0 = pB + (j*8 + g) * AST + ks + l4;
                bf[j][0] = __float_as_uint(p0[0]);
                bf[j][1] = __float_as_uint(p0[4]);
            }
            #pragma unroll
            for (int i = 0; i < 4; i++)
                #pragma unroll
                for (int j = 0; j < 8; j++)
                    mma8(acc[i][j], af[i], bf[j]);
        }
        s = (s == NSTAGE - 1) ? 0 : s + 1;
    }

    #pragma unroll
    for (int i = 0; i < 4; i++) {
        const int r0 = brow + mb + i*16 + g;
        #pragma unroll
        for (int j = 0; j < 8; j++) {
            const int col = bn + nb + j*8 + 2*l4;
            float b0 = bias[col], b1 = bias[col + 1];
            float v0 = acc[i][j][0] + b0, v1 = acc[i][j][1] + b1;
            float v2 = acc[i][j][2] + b0, v3 = acc[i][j][3] + b1;
            if (ROUND_OUT) {
                v0 = __uint_as_float(f2tf(v0)); v1 = __uint_as_float(f2tf(v1));
                v2 = __uint_as_float(f2tf(v2)); v3 = __uint_as_float(f2tf(v3));
            }
            float2 w0 = {v0, v1}, w1 = {v2, v3};
            *(float2*)&C[(size_t)r0 * HIDDEN + col]       = w0;
            *(float2*)&C[(size_t)(r0 + 8) * HIDDEN + col] = w1;
        }
    }
}

// ---------------------------------------------------------------------------
// Flash attention, tf32 mma.sync, register-resident log2-domain softmax.
// 128 q-rows per block (512 threads, 16 warps), 128 keys per iter.
//   mb=(warp&3)*32 picks q block; wc=warp>>2 picks 32-wide key block (QK)
//   or 32-wide headdim block (PV).
// S tile ALIASES the K tile: K is dead after QK^T (all reads complete before
// the sync(3) that precedes S stores); next iteration's K cp.async lands only
// after sync(1), which follows all PV reads of S.
// cp.async: K committed first, V second -> wait_group(1) gates QK on K only.
// ---------------------------------------------------------------------------
#define AQ  128
#define AKK 128
#define QW  132    // row stride (floats): 128 + 4 pad
// smem float offsets
#define OQ  0
#define OK  (AQ*QW)                 // 16896   (K tile; S aliases this)
#define OV  (OK + AKK*QW)           // 33792
#define OMX (OV + AKK*QW)           // 50688
#define OL  (OMX + AQ)              // 50816
#define OPM (OL + AQ)               // 50944   pmax[4][128]
#define OPS (OPM + 512)             // 51456   psum[4][128]
#define ATT_FLOATS (OPS + 512)      // 51968
#define ATT_SMEM (ATT_FLOATS * 4)   // 207872 bytes

__global__ __launch_bounds__(512, 1) void attn_tf32(
    const float* __restrict__ Q, const float* __restrict__ K,
    const float* __restrict__ V, const float* __restrict__ mask,
    float* __restrict__ O)
{
    extern __shared__ float sm[];
    const uint32_t sbase = smem_u32(sm);
    float* sQ  = sm + OQ;
    float* sK  = sm + OK;
    float* sV  = sm + OV;
    float* sS  = sm + OK;      // alias: S overwrites K after QK^T
    float* sMx = sm + OMX;
    float* sL  = sm + OL;
    float* pmax = sm + OPM;
    float* psum = sm + OPS;

    const int tid  = threadIdx.x;
    const int lane = tid & 31;
    const int warp = tid >> 5;
    const int g    = lane >> 2;
    const int l4   = lane & 3;
    const int mb   = (warp & 3) * 32;
    const int wc   = warp >> 2;
    const int cb   = wc * 32;
    const int qt = blockIdx.x, h = blockIdx.y, b = blockIdx.z;
    const size_t base = (size_t)b * SEQ * HIDDEN + (size_t)h * HDIM;

    // resident Q tile (already tf32-rounded bits)
    for (int it = tid; it < AQ*HDIM/4; it += 512) {
        int r = it >> 5, c = (it & 31) * 4;
        *(float4*)&sQ[r*QW + c] =
            *(const float4*)&Q[base + (size_t)(qt*AQ + r)*HIDDEN + c];
    }
    if (tid < AQ) { sMx[tid] = -1e30f; sL[tid] = 0.f; }

    float oacc[2][4][4];
    #pragma unroll
    for (int i = 0; i < 2; i++)
        #pragma unroll
        for (int j = 0; j < 4; j++)
            #pragma unroll
            for (int t = 0; t < 4; t++) oacc[i][j][t] = 0.f;

    for (int kt = 0; kt < SEQ/AKK; kt++) {      // 16 iterations
        __syncthreads();   // (1) prior PV done: K/S, V buffers + partials free

        // issue K loads (group 1), then V loads (group 2)
        {
            const uint32_t kdst = sbase + OK*4;
            const uint32_t vdst = sbase + OV*4;
            #pragma unroll
            for (int i = 0; i < 8; i++) {
                int it = tid + i*512;
                int r = it >> 5, c = (it & 31) * 4;
                cpa16(kdst + (r*QW + c)*4,
                      &K[base + (size_t)(kt*AKK + r)*HIDDEN + c]);
            }
            CP_COMMIT();
            #pragma unroll
            for (int i = 0; i < 8; i++) {
                int it = tid + i*512;
                int r = it >> 5, c = (it & 31) * 4;
                cpa16(vdst + (r*QW + c)*4,
                      &V[base + (size_t)(kt*AKK + r)*HIDDEN + c]);
            }
            CP_COMMIT();
        }

        // mask values for this tile (log2 domain), overlap with K load
        float ml[4][2];
        {
            const float* mrow = &mask[(size_t)b*SEQ + kt*AKK];
            #pragma unroll
            for (int j = 0; j < 4; j++) {
                float2 mv = *(const float2*)&mrow[cb + j*8 + 2*l4];
                ml[j][0] = mv.x * LOG2E;
                ml[j][1] = mv.y * LOG2E;
            }
        }

        CP_WAIT(1);        // K arrived (V may still be in flight)
        __syncthreads();   // (2) K visible to all warps

        // ---- S = Q K^T on warp tile [mb:mb+32] x [cb:cb+32]
        float sacc[2][4][4];
        #pragma unroll
        for (int i = 0; i < 2; i++)
            #pragma unroll
            for (int j = 0; j < 4; j++)
                #pragma unroll
                for (int t = 0; t < 4; t++) sacc[i][j][t] = 0.f;

        #pragma unroll
        for (int ks = 0; ks < HDIM; ks += 8) {
            unsigned af[2][4], bf[4][2];
            #pragma unroll
            for (int i = 0; i < 2; i++) {
                const float* p0 = &sQ[(mb + i*16 + g)*QW + ks + l4];
                af[i][0] = __float_as_uint(p0[0]);
                af[i][1] = __float_as_uint(p0[8*QW]);
                af[i][2] = __float_as_uint(p0[4]);
                af[i][3] = __float_as_uint(p0[8*QW + 4]);
            }
            #pragma unroll
            for (int j = 0; j < 4; j++) {
                const float* p0 = &sK[(cb + j*8 + g)*QW + ks + l4];
                bf[j][0] = __float_as_uint(p0[0]);
                bf[j][1] = __float_as_uint(p0[4]);
            }
            #pragma unroll
            for (int i = 0; i < 2; i++)
                #pragma unroll
                for (int j = 0; j < 4; j++)
                    mma8(sacc[i][j], af[i], bf[j]);
        }

        // scale + mask in log2 domain (registers)
        #pragma unroll
        for (int i = 0; i < 2; i++)
            #pragma unroll
            for (int j = 0; j < 4; j++) {
                sacc[i][j][0] = sacc[i][j][0]*SCALE2 + ml[j][0];
                sacc[i][j][1] = sacc[i][j][1]*SCALE2 + ml[j][1];
                sacc[i][j][2] = sacc[i][j][2]*SCALE2 + ml[j][0];
                sacc[i][j][3] = sacc[i][j][3]*SCALE2 + ml[j][1];
            }

        // ---- per-row max partials (registers + quad shuffles)
        float mloc[2][2];
        #pragma unroll
        for (int i = 0; i < 2; i++)
            #pragma unroll
            for (int p = 0; p < 2; p++) {
                float m = -1e30f;
                #pragma unroll
                for (int j = 0; j < 4; j++)
                    m = fmaxf(m, fmaxf(sacc[i][j][2*p], sacc[i][j][2*p+1]));
                m = fmaxf(m, __shfl_xor_sync(0xffffffffu, m, 1));
                m = fmaxf(m, __shfl_xor_sync(0xffffffffu, m, 2));
                mloc[i][p] = m;
            }
        if (l4 == 0) {
            #pragma unroll
            for (int i = 0; i < 2; i++)
                #pragma unroll
                for (int p = 0; p < 2; p++)
                    pmax[wc*AQ + mb + i*16 + p*8 + g] = mloc[i][p];
        }
        __syncthreads();   // (3) pmax visible; ALL K reads complete (S may now overwrite K)

        // ---- combine maxes, exponentiate in registers, store P (into K region), sum
        float mtv[2][2], fv[2][2], lsum[2][2];
        #pragma unroll
        for (int i = 0; i < 2; i++)
            #pragma unroll
            for (int p = 0; p < 2; p++) {
                int r = mb + i*16 + p*8 + g;
                float mo = sMx[r];
                float mt = fmaxf(fmaxf(pmax[r], pmax[AQ+r]),
                                 fmaxf(pmax[2*AQ+r], pmax[3*AQ+r]));
                mt = fmaxf(mo, mt);
                mtv[i][p] = mt;
                fv[i][p]  = ex2(mo - mt);
                lsum[i][p] = 0.f;
            }
        #pragma unroll
        for (int i = 0; i < 2; i++)
            #pragma unroll
            for (int j = 0; j < 4; j++)
                #pragma unroll
                for (int p = 0; p < 2; p++) {
                    float p0 = __uint_as_float(f2tf(ex2(sacc[i][j][2*p]   - mtv[i][p])));
                    float p1 = __uint_as_float(f2tf(ex2(sacc[i][j][2*p+1] - mtv[i][p])));
                    lsum[i][p] += p0 + p1;
                    float2 pv = {p0, p1};
                    *(float2*)&sS[(mb + i*16 + p*8 + g)*QW + cb + j*8 + 2*l4] = pv;
                }
        #pragma unroll
        for (int i = 0; i < 2; i++)
            #pragma unroll
            for (int p = 0; p < 2; p++) {
                float l = lsum[i][p];
                l += __shfl_xor_sync(0xffffffffu, l, 1);
                l += __shfl_xor_sync(0xffffffffu, l, 2);
                lsum[i][p] = l;
            }
        if (l4 == 0) {
            #pragma unroll
            for (int i = 0; i < 2; i++)
                #pragma unroll
                for (int p = 0; p < 2; p++)
                    psum[wc*AQ + mb + i*16 + p*8 + g] = lsum[i][p];
        }

        CP_WAIT(0);        // V arrived (own thread)
        __syncthreads();   // (4) psum + P + V visible

        // owner updates running stats (read next iter after syncs 1-3)
        if (wc == 0 && l4 == 0) {
            #pragma unroll
            for (int i = 0; i < 2; i++)
                #pragma unroll
                for (int p = 0; p < 2; p++) {
                    int r = mb + i*16 + p*8 + g;
                    float ls = psum[r] + psum[AQ+r] + psum[2*AQ+r] + psum[3*AQ+r];
                    sL[r]  = sL[r]*fv[i][p] + ls;
                    sMx[r] = mtv[i][p];
                }
        }

        // rescale O and accumulate P V
        #pragma unroll
        for (int i = 0; i < 2; i++)
            #pragma unroll
            for (int j = 0; j < 4; j++) {
                oacc[i][j][0] *= fv[i][0]; oacc[i][j][1] *= fv[i][0];
                oacc[i][j][2] *= fv[i][1]; oacc[i][j][3] *= fv[i][1];
            }
        #pragma unroll
        for (int ks = 0; ks < AKK; ks += 8) {
            unsigned af[2][4], bf[4][2];
            #pragma unroll
            for (int i = 0; i < 2; i++) {
                const float* p0 = &sS[(mb + i*16 + g)*QW + ks + l4];
                af[i][0] = __float_as_uint(p0[0]);
                af[i][1] = __float_as_uint(p0[8*QW]);
                af[i][2] = __float_as_uint(p0[4]);
                af[i][3] = __float_as_uint(p0[8*QW + 4]);
            }
            #pragma unroll
            for (int j = 0; j < 4; j++) {
                const float* p0 = &sV[(ks + l4)*QW + cb + j*8 + g];
                bf[j][0] = __float_as_uint(p0[0]);
                bf[j][1] = __float_as_uint(p0[4*QW]);
            }
            #pragma unroll
            for (int i = 0; i < 2; i++)
                #pragma unroll
                for (int j = 0; j < 4; j++)
                    mma8(oacc[i][j], af[i], bf[j]);
        }
    }

    __syncthreads();       // final sL updates visible

    // normalize + write (tf32-rounded so Wo GEMM's A is pre-rounded)
    #pragma unroll
    for (int i = 0; i < 2; i++) {
        float i0 = 1.f / sL[mb + i*16 + g];
        float i1 = 1.f / sL[mb + i*16 + g + 8];
        #pragma unroll
        for (int j = 0; j < 4; j++) {
            int col = cb + j*8 + 2*l4;
            size_t r0 = base + (size_t)(qt*AQ + mb + i*16 + g    )*HIDDEN + col;
            size_t r1 = base + (size_t)(qt*AQ + mb + i*16 + g + 8)*HIDDEN + col;
            float2 v0 = { __uint_as_float(f2tf(oacc[i][j][0]*i0)),
                          __uint_as_float(f2tf(oacc[i][j][1]*i0)) };
            float2 v1 = { __uint_as_float(f2tf(oacc[i][j][2]*i1)),
                          __uint_as_float(f2tf(oacc[i][j][3]*i1)) };
            *(float2*)&O[r0] = v0;
            *(float2*)&O[r1] = v1;
        }
    }
}

// ---------------------------------------------------------------------------
extern "C" void kernel_launch(void* const* d_in, const int* in_sizes, int n_in,
                              void* d_out, int out_size) {
    const float* X    = (const float*)d_in[0];
    const float* mask = (const float*)d_in[1];
    const float* Wq   = (const float*)d_in[2];
    const float* bq   = (const float*)d_in[3];
    const float* Wk   = (const float*)d_in[4];
    const float* bk   = (const float*)d_in[5];
    const float* Wv   = (const float*)d_in[6];
    const float* bv   = (const float*)d_in[7];
    const float* Wo   = (const float*)d_in[8];
    const float* bo   = (const float*)d_in[9];
    float* out = (float*)d_out;

    float *qp, *kp, *vp, *cp, *xr, *wr;
    cudaGetSymbolAddress((void**)&qp, g_Q);
    cudaGetSymbolAddress((void**)&kp, g_K);
    cudaGetSymbolAddress((void**)&vp, g_V);
    cudaGetSymbolAddress((void**)&cp, g_C);
    cudaGetSymbolAddress((void**)&xr, g_Xr);
    cudaGetSymbolAddress((void**)&wr, g_Wr);

    const int NX4 = ROWS*HIDDEN/4, NW4 = HIDDEN*HIDDEN/4;
    round_tf32_kernel<<<(NX4+255)/256, 256>>>(X, xr, NX4);
    WPtrs ws; ws.w[0] = Wq; ws.w[1] = Wk; ws.w[2] = Wv; ws.w[3] = Wo;
    round_w4_kernel<<<(4*NW4)/256, 256>>>(ws, wr, NW4);

    cudaFuncSetAttribute(tf32_gemm<true>,  cudaFuncAttributeMaxDynamicSharedMemorySize, GEMM_SMEM);
    cudaFuncSetAttribute(tf32_gemm<false>, cudaFuncAttributeMaxDynamicSharedMemorySize, GEMM_SMEM);

    dim3 ggrid(HIDDEN/GBN, ROWS/GBM);   // (8, 32)
    tf32_gemm<true><<<ggrid, 256, GEMM_SMEM>>>(xr, wr + 0*HIDDEN*HIDDEN, bq, qp);
    tf32_gemm<true><<<ggrid, 256, GEMM_SMEM>>>(xr, wr + 1*HIDDEN*HIDDEN, bk, kp);
    tf32_gemm<true><<<ggrid, 256, GEMM_SMEM>>>(xr, wr + 2*HIDDEN*HIDDEN, bv, vp);

    cudaFuncSetAttribute(attn_tf32, cudaFuncAttributeMaxDynamicSharedMemorySize, (int)ATT_SMEM);
    dim3 agrid(SEQ/AQ, NHEADS, BATCH);  // (16, 16, 2)
    attn_tf32<<<agrid, 512, ATT_SMEM>>>(qp, kp, vp, mask, cp);

    tf32_gemm<false><<<ggrid, 256, GEMM_SMEM>>>(cp, wr + 3*HIDDEN*HIDDEN, bo, out);
}